// round 3
// baseline (speedup 1.0000x reference)
#include <cuda_runtime.h>

#define BATCH 512
#define SEQT  1024
#define FEATD 128
#define UNITS 50
#define NG    200   // 4*UNITS
#define TCH   128   // timesteps per chunk
#define NCH   (SEQT / TCH)   // 8 chunks

// Chunk scratch: Z = X @ kernel + bias for one time-chunk,
// [BATCH * TCH, 200] fp32 = 52.4 MB (static device global; reused per chunk)
__device__ float g_Z[(size_t)BATCH * TCH * NG];
// LSTM state carried across chunk launches
__device__ float g_h[BATCH * UNITS];
__device__ float g_c[BATCH * UNITS];

// ---------------------------------------------------------------------------
// Kernel 1: chunk pregemm.  Block b computes Z for batch b's TCH timesteps:
//   Z[b*TCH + lt, c] = bias[c] + sum_k X[b, c0+lt, k] * Wk[k, c]
//   128 rows x 200 cols per block, K chunked by 32. 256 threads = 8 warps.
//   Warp w owns cols [25w, 25w+25); lane l owns rows {l, l+32, l+64, l+96}.
// ---------------------------------------------------------------------------
__global__ __launch_bounds__(256) void pregemm_kernel(
    const float* __restrict__ X, const float* __restrict__ Wk,
    const float* __restrict__ bias, int c0)
{
    __shared__ float ws[32 * NG];     // 25.6 KB  (W chunk, row-major [32][200])
    __shared__ float xs[128 * 33];    // 16.9 KB  (X chunk, stride 33 -> conflict-free)

    const int tid = threadIdx.x;
    const int w   = tid >> 5;
    const int l   = tid & 31;
    const int wc  = w * 25;

    float acc[4][25];
    #pragma unroll
    for (int j = 0; j < 25; ++j) {
        float bv = bias[wc + j];
        acc[0][j] = bv; acc[1][j] = bv; acc[2][j] = bv; acc[3][j] = bv;
    }

    // X rows for this block: [b*SEQT + c0, +128)  (contiguous, coalesced)
    const size_t xrow0 = (size_t)blockIdx.x * SEQT + c0;
    const float4* X4 = (const float4*)(X + xrow0 * FEATD);
    const float4* K4 = (const float4*)Wk;

    for (int kk = 0; kk < 4; ++kk) {
        __syncthreads();
        // W chunk: rows [kk*32, kk*32+32) of [128,200] = 1600 float4
        float4* ws4 = (float4*)ws;
        for (int idx = tid; idx < 1600; idx += 256)
            ws4[idx] = K4[kk * 1600 + idx];
        // X chunk: 128 rows x 32 k's = 1024 float4 (8 float4 per row)
        for (int idx = tid; idx < 1024; idx += 256) {
            int r = idx >> 3;
            int q = idx & 7;
            float4 v = X4[(size_t)r * 32 + kk * 8 + q];
            float* p = &xs[r * 33 + q * 4];
            p[0] = v.x; p[1] = v.y; p[2] = v.z; p[3] = v.w;
        }
        __syncthreads();

        #pragma unroll
        for (int k = 0; k < 32; ++k) {
            float x0 = xs[(l      ) * 33 + k];
            float x1 = xs[(l + 32 ) * 33 + k];
            float x2 = xs[(l + 64 ) * 33 + k];
            float x3 = xs[(l + 96 ) * 33 + k];
            const float* wr = &ws[k * NG + wc];
            #pragma unroll
            for (int j = 0; j < 25; ++j) {
                float wv = wr[j];
                acc[0][j] = fmaf(x0, wv, acc[0][j]);
                acc[1][j] = fmaf(x1, wv, acc[1][j]);
                acc[2][j] = fmaf(x2, wv, acc[2][j]);
                acc[3][j] = fmaf(x3, wv, acc[3][j]);
            }
        }
    }

    // Z rows for this block: [b*TCH, +128) in chunk-local scratch
    const size_t zrow0 = (size_t)blockIdx.x * TCH;
    #pragma unroll
    for (int i = 0; i < 4; ++i) {
        float* zp = g_Z + (zrow0 + l + 32 * i) * NG + wc;
        #pragma unroll
        for (int j = 0; j < 25; ++j) zp[j] = acc[i][j];
    }
}

// ---------------------------------------------------------------------------
// Kernel 2: per-row LSTM recurrence over one time-chunk + dense head at end.
//   One block per batch row (512 blocks, 128 threads, 4 blocks/SM => 1 wave).
//   rec_kernel columns live in registers (thread j owns cols j and j+128;
//   threads j>=72 own only col j and run a half-width FMA loop).
//   z_t prefetched one timestep ahead to hide DRAM/L2 latency.
//   (h, c) persisted in g_h/g_c between chunk launches.
// ---------------------------------------------------------------------------
__device__ __forceinline__ float sigmoid_f(float x) {
    return __fdividef(1.0f, 1.0f + __expf(-x));
}
__device__ __forceinline__ float tanh_f(float x) {
    return 2.0f * sigmoid_f(2.0f * x) - 1.0f;
}

__global__ __launch_bounds__(128, 4) void lstm_recur_kernel(
    const float* __restrict__ rec_kernel,
    const float* __restrict__ dense_w,
    const float* __restrict__ dense_b,
    float* __restrict__ out, int chunk)
{
    __shared__ float hs[UNITS];   // hidden state (broadcast)
    __shared__ float act[NG];     // activated gate values i|f|g|o

    const int j = threadIdx.x;
    const int b = blockIdx.x;
    const bool two = (j < NG - 128);      // j < 72 handles a second column
    const int  c1  = j + 128;

    // Per-thread recurrent weight columns in registers
    float w0[UNITS], w1[UNITS];
    #pragma unroll
    for (int u = 0; u < UNITS; ++u) {
        w0[u] = rec_kernel[u * NG + j];
        w1[u] = two ? rec_kernel[u * NG + c1] : 0.0f;
    }
    const bool tgate0 = (j >= 100 && j < 150);  // col j is the 'g' gate -> tanh
    const bool tgate1 = (c1 < 150);             // col j+128 in [128,150) -> tanh

    float creg = 0.0f;
    if (j < UNITS) {
        if (chunk == 0) {
            hs[j] = 0.0f;
        } else {
            hs[j] = g_h[b * UNITS + j];
            creg  = g_c[b * UNITS + j];
        }
    }
    __syncthreads();

    const float* zp = g_Z + (size_t)b * TCH * NG;
    float z0 = zp[j];
    float z1 = two ? zp[c1] : 0.0f;

    for (int t = 0; t < TCH; ++t) {
        // prefetch next step's z (last iter re-reads current row; discarded)
        const float* znext = zp + ((t < TCH - 1) ? NG : 0);
        float nz0 = __ldg(znext + j);
        float nz1 = two ? __ldg(znext + c1) : 0.0f;

        // z_col += h . rec_col   (two interleaved accumulator chains per col)
        float v0, v1 = 0.0f;
        if (two) {
            float a0 = z0, b0 = 0.0f, a1 = z1, b1 = 0.0f;
            #pragma unroll
            for (int u = 0; u < UNITS; u += 2) {
                float h0 = hs[u], h1 = hs[u + 1];
                a0 = fmaf(h0, w0[u],     a0);
                b0 = fmaf(h1, w0[u + 1], b0);
                a1 = fmaf(h0, w1[u],     a1);
                b1 = fmaf(h1, w1[u + 1], b1);
            }
            v0 = a0 + b0;
            v1 = a1 + b1;
        } else {
            float a0 = z0, b0 = 0.0f;
            #pragma unroll
            for (int u = 0; u < UNITS; u += 2) {
                a0 = fmaf(hs[u],     w0[u],     a0);
                b0 = fmaf(hs[u + 1], w0[u + 1], b0);
            }
            v0 = a0 + b0;
        }
        act[j] = tgate0 ? tanh_f(v0) : sigmoid_f(v0);
        if (two) act[c1] = tgate1 ? tanh_f(v1) : sigmoid_f(v1);
        __syncthreads();

        if (j < UNITS) {
            float ig = act[j] * act[100 + j];           // sig(i)*tanh(g)
            creg = fmaf(act[50 + j], creg, ig);         // f*c + i*g
            hs[j] = act[150 + j] * tanh_f(creg);        // o*tanh(c)
        }
        __syncthreads();

        z0 = nz0; z1 = nz1; zp += NG;
    }

    if (j < UNITS) {
        g_h[b * UNITS + j] = hs[j];
        g_c[b * UNITS + j] = creg;
    }

    if (chunk == NCH - 1 && j == 0) {
        float s = dense_b[0];
        #pragma unroll
        for (int u = 0; u < UNITS; ++u) s = fmaf(hs[u], dense_w[u], s);
        out[b] = s;
    }
}

// ---------------------------------------------------------------------------
extern "C" void kernel_launch(void* const* d_in, const int* in_sizes, int n_in,
                              void* d_out, int out_size) {
    const float* X    = (const float*)d_in[0];  // [512,1024,128]
    const float* Wk   = (const float*)d_in[1];  // [128,200]
    const float* Wr   = (const float*)d_in[2];  // [50,200]
    const float* bias = (const float*)d_in[3];  // [200]
    const float* dw   = (const float*)d_in[4];  // [50,1]
    const float* db   = (const float*)d_in[5];  // [1]
    float* out = (float*)d_out;                 // [512,1]

    for (int c = 0; c < NCH; ++c) {
        pregemm_kernel<<<BATCH, 256>>>(X, Wk, bias, c * TCH);
        lstm_recur_kernel<<<BATCH, 128>>>(Wr, dw, db, out, c);
    }
}

// round 4
// speedup vs baseline: 1.0726x; 1.0726x over previous
#include <cuda_runtime.h>

#define BATCH 512
#define SEQT  1024
#define FEATD 128
#define UNITS 50
#define NG    200   // 4*UNITS
#define TCH   128   // timesteps per chunk
#define NCH   (SEQT / TCH)   // 8 chunks

// Chunk scratch: Z = X @ kernel + bias for one time-chunk,
// [BATCH * TCH, 200] fp32 = 52.4 MB (static device global; reused per chunk)
__device__ float g_Z[(size_t)BATCH * TCH * NG];
// LSTM state carried across chunk launches
__device__ float g_h[BATCH * UNITS];
__device__ float g_c[BATCH * UNITS];

typedef unsigned long long ull;

// ---- packed f32x2 helpers (Blackwell FFMA2/FADD2) -------------------------
__device__ __forceinline__ void fma2(ull& d, ull a, ull b) {
    asm("fma.rn.f32x2 %0, %1, %2, %0;" : "+l"(d) : "l"(a), "l"(b));
}
__device__ __forceinline__ ull add2(ull a, ull b) {
    ull r; asm("add.rn.f32x2 %0, %1, %2;" : "=l"(r) : "l"(a), "l"(b)); return r;
}
__device__ __forceinline__ ull splat2(float x) {
    ull r; asm("mov.b64 %0, {%1, %1};" : "=l"(r) : "f"(x)); return r;
}
__device__ __forceinline__ ull pack2(float lo, float hi) {
    ull r; asm("mov.b64 %0, {%1, %2};" : "=l"(r) : "f"(lo), "f"(hi)); return r;
}
__device__ __forceinline__ float2 unpack2(ull v) {
    float2 r; asm("mov.b64 {%0, %1}, %2;" : "=f"(r.x), "=f"(r.y) : "l"(v)); return r;
}

// ---------------------------------------------------------------------------
// Kernel 1: chunk pregemm with packed f32x2 math.
//   Z[b*TCH + lt, c] = bias[c] + sum_k X[b, c0+lt, k] * Wk[k, c]
//   Block b: 128 rows (batch b's TCH timesteps) x 200 cols, K chunked by 32.
//   320 threads = 10 warps. Warp w owns cols [20w, 20w+20) as 10 f32x2 pairs;
//   lane l owns rows {l, l+32, l+64, l+96}.
// ---------------------------------------------------------------------------
__global__ __launch_bounds__(320) void pregemm_kernel(
    const float* __restrict__ X, const float* __restrict__ Wk,
    const float* __restrict__ bias, int c0)
{
    __shared__ float ws[32 * NG];     // 25.6 KB  (W chunk, row-major [32][200])
    __shared__ float xs[128 * 33];    // 16.9 KB  (X chunk, stride 33 -> conflict-free)

    const int tid = threadIdx.x;
    const int w   = tid >> 5;
    const int l   = tid & 31;
    const int wc  = w * 20;

    // packed accumulators: 4 row-groups x 10 column-pairs
    ull acc0[10], acc1[10], acc2[10], acc3[10];
    {
        const ull* b2 = (const ull*)(bias + wc);   // 8B-aligned (wc even)
        #pragma unroll
        for (int jj = 0; jj < 10; ++jj) {
            ull bv = b2[jj];
            acc0[jj] = bv; acc1[jj] = bv; acc2[jj] = bv; acc3[jj] = bv;
        }
    }

    // X rows for this block: [b*SEQT + c0, +128)  (contiguous, coalesced)
    const size_t xrow0 = (size_t)blockIdx.x * SEQT + c0;
    const float4* X4 = (const float4*)(X + xrow0 * FEATD);
    const float4* K4 = (const float4*)Wk;

    for (int kk = 0; kk < 4; ++kk) {
        __syncthreads();
        // W chunk: rows [kk*32, kk*32+32) of [128,200] = 1600 float4
        float4* ws4 = (float4*)ws;
        for (int idx = tid; idx < 1600; idx += 320)
            ws4[idx] = K4[kk * 1600 + idx];
        // X chunk: 128 rows x 32 k's = 1024 float4 (8 float4 per row)
        for (int idx = tid; idx < 1024; idx += 320) {
            int r = idx >> 3;
            int q = idx & 7;
            float4 v = X4[(size_t)r * 32 + kk * 8 + q];
            float* p = &xs[r * 33 + q * 4];
            p[0] = v.x; p[1] = v.y; p[2] = v.z; p[3] = v.w;
        }
        __syncthreads();

        #pragma unroll 4
        for (int k = 0; k < 32; ++k) {
            ull xp0 = splat2(xs[(l      ) * 33 + k]);
            ull xp1 = splat2(xs[(l + 32 ) * 33 + k]);
            ull xp2 = splat2(xs[(l + 64 ) * 33 + k]);
            ull xp3 = splat2(xs[(l + 96 ) * 33 + k]);
            const ull* wr = (const ull*)&ws[k * NG + wc];   // 8B-aligned
            #pragma unroll
            for (int jj = 0; jj < 10; ++jj) {
                ull wv = wr[jj];                            // LDS.64 broadcast
                fma2(acc0[jj], xp0, wv);
                fma2(acc1[jj], xp1, wv);
                fma2(acc2[jj], xp2, wv);
                fma2(acc3[jj], xp3, wv);
            }
        }
    }

    // Z rows for this block: [b*TCH, +128) in chunk-local scratch
    const size_t zrow0 = (size_t)blockIdx.x * TCH;
    #pragma unroll
    for (int i = 0; i < 4; ++i) {
        float2* zp = (float2*)(g_Z + (zrow0 + l + 32 * i) * NG + wc);
        ull* ai = (i == 0) ? acc0 : (i == 1) ? acc1 : (i == 2) ? acc2 : acc3;
        #pragma unroll
        for (int jj = 0; jj < 10; ++jj) zp[jj] = unpack2(ai[jj]);
    }
}

// ---------------------------------------------------------------------------
// Kernel 2: per-row LSTM recurrence over one time-chunk + dense head at end.
//   One block per batch row (512 blocks, 128 threads, 4 blocks/SM => 1 wave).
//   Thread j < 100 owns column PAIR (j, j+100) with packed f32x2 weights in
//   registers (50 x ull). hidden state kept pre-splatted in smem (float2) so
//   each LDS.64 broadcast directly feeds one FMA2.
//   Gate map: col j -> sigmoid (i if j<50 else f); col j+100 -> tanh if j<50
//   (g gate) else sigmoid (o gate).
// ---------------------------------------------------------------------------
__device__ __forceinline__ float sigmoid_f(float x) {
    return __fdividef(1.0f, 1.0f + __expf(-x));
}
__device__ __forceinline__ float tanh_f(float x) {
    return 2.0f * sigmoid_f(2.0f * x) - 1.0f;
}

__global__ __launch_bounds__(128, 4) void lstm_recur_kernel(
    const float* __restrict__ rec_kernel,
    const float* __restrict__ dense_w,
    const float* __restrict__ dense_b,
    float* __restrict__ out, int chunk)
{
    __shared__ float2 hs2[UNITS];   // hidden state, pre-splatted (h,h)
    __shared__ float  act[NG];      // activated gates i|f|g|o

    const int j = threadIdx.x;
    const int b = blockIdx.x;
    const bool active = (j < 100);

    // Packed recurrent weight pairs: wp[u] = (Wr[u][j], Wr[u][j+100])
    ull wp[UNITS];
    if (active) {
        #pragma unroll
        for (int u = 0; u < UNITS; ++u)
            wp[u] = pack2(rec_kernel[u * NG + j], rec_kernel[u * NG + j + 100]);
    }
    const bool tg = (j < 50);   // second column is the tanh 'g' gate

    float creg = 0.0f;
    if (j < UNITS) {
        float h0 = 0.0f;
        if (chunk != 0) {
            h0   = g_h[b * UNITS + j];
            creg = g_c[b * UNITS + j];
        }
        hs2[j] = make_float2(h0, h0);
    }
    __syncthreads();

    const float* zrow = g_Z + (size_t)b * TCH * NG;
    float z0 = 0.0f, z1 = 0.0f;
    if (active) { z0 = zrow[j]; z1 = zrow[j + 100]; }

    for (int t = 0; t < TCH; ++t) {
        // prefetch next step's z (last iter re-reads current row; discarded)
        const float* znext = zrow + ((t < TCH - 1) ? NG : 0);
        float nz0 = 0.0f, nz1 = 0.0f;
        if (active) { nz0 = __ldg(znext + j); nz1 = __ldg(znext + j + 100); }

        if (active) {
            ull accA = pack2(z0, z1);
            ull accB = pack2(0.0f, 0.0f);
            const ull* hp = (const ull*)hs2;
            #pragma unroll
            for (int u = 0; u < UNITS; u += 2) {
                fma2(accA, hp[u],     wp[u]);       // LDS.64 broadcast of (h,h)
                fma2(accB, hp[u + 1], wp[u + 1]);
            }
            float2 v = unpack2(add2(accA, accB));
            act[j]       = sigmoid_f(v.x);
            act[j + 100] = tg ? tanh_f(v.y) : sigmoid_f(v.y);
        }
        __syncthreads();

        if (j < UNITS) {
            float ig = act[j] * act[100 + j];        // sig(i) * tanh(g)
            creg = fmaf(act[50 + j], creg, ig);      // f*c + i*g
            float h = act[150 + j] * tanh_f(creg);   // o * tanh(c)
            hs2[j] = make_float2(h, h);
        }
        __syncthreads();

        z0 = nz0; z1 = nz1; zrow += NG;
    }

    if (j < UNITS) {
        g_h[b * UNITS + j] = hs2[j].x;
        g_c[b * UNITS + j] = creg;
    }

    if (chunk == NCH - 1 && j == 0) {
        float s = dense_b[0];
        #pragma unroll
        for (int u = 0; u < UNITS; ++u) s = fmaf(hs2[u].x, dense_w[u], s);
        out[b] = s;
    }
}

// ---------------------------------------------------------------------------
extern "C" void kernel_launch(void* const* d_in, const int* in_sizes, int n_in,
                              void* d_out, int out_size) {
    const float* X    = (const float*)d_in[0];  // [512,1024,128]
    const float* Wk   = (const float*)d_in[1];  // [128,200]
    const float* Wr   = (const float*)d_in[2];  // [50,200]
    const float* bias = (const float*)d_in[3];  // [200]
    const float* dw   = (const float*)d_in[4];  // [50,1]
    const float* db   = (const float*)d_in[5];  // [1]
    float* out = (float*)d_out;                 // [512,1]

    for (int c = 0; c < NCH; ++c) {
        pregemm_kernel<<<BATCH, 320>>>(X, Wk, bias, c * TCH);
        lstm_recur_kernel<<<BATCH, 128>>>(Wr, dw, db, out, c);
    }
}